// round 16
// baseline (speedup 1.0000x reference)
#include <cuda_runtime.h>
#include <cuda_fp16.h>
#include <cstdint>

#define VOCAB   250002
#define BATCH   16
#define SEQ     2048
#define HDIM    1024
#define SM1     2047               // SEQ-1
#define MROWS   (BATCH * SM1)      // 32752
#define NTOK    (BATCH * SEQ)      // 32768
#define EPSN    1e-12f

// ===================== small helpers =====================
static __device__ __forceinline__ uint32_t smem_u32(const void* p) {
    uint32_t a;
    asm("{ .reg .u64 t; cvta.to.shared.u64 t, %1; cvt.u32.u64 %0, t; }" : "=r"(a) : "l"(p));
    return a;
}
// pack two floats to f16x2 (first arg -> low half)
static __device__ __forceinline__ unsigned hpack(float lo, float hi) {
    unsigned r;
    asm("cvt.rn.f16x2.f32 %0, %1, %2;" : "=r"(r) : "f"(hi), "f"(lo));
    return r;
}

#define CP_ASYNC16(s, g) \
    asm volatile("cp.async.cg.shared.global [%0], [%1], 16;" :: "r"(s), "l"(g))
#define CP_COMMIT()  asm volatile("cp.async.commit_group;" ::: "memory")
#define CP_WAIT2()   asm volatile("cp.async.wait_group 2;" ::: "memory")

#define LDSM4(R, a) \
    asm volatile("ldmatrix.sync.aligned.m8n8.x4.shared.b16 {%0,%1,%2,%3}, [%4];" \
        : "=r"((R)[0]), "=r"((R)[1]), "=r"((R)[2]), "=r"((R)[3]) : "r"(a))

#define MMA16816(D, A, B0, B1) \
    asm volatile("mma.sync.aligned.m16n8k16.row.col.f32.f16.f16.f32 " \
        "{%0,%1,%2,%3}, {%4,%5,%6,%7}, {%8,%9}, {%0,%1,%2,%3};" \
        : "+f"((D)[0]), "+f"((D)[1]), "+f"((D)[2]), "+f"((D)[3]) \
        : "r"((A)[0]), "r"((A)[1]), "r"((A)[2]), "r"((A)[3]), "r"(B0), "r"(B1))

// ===================== device scratch =====================
__device__ __half g_Wt[HDIM * HDIM];               // [N, K] K-contig, fp16
__device__ __half g_Ah[(size_t)NTOK * HDIM];       // hidden fp16, token order
__device__ __half g_Craw[(size_t)MROWS * HDIM];    // raw colbert output, fp16

// ===================== W pre-transpose, fp16 =====================
__global__ __launch_bounds__(256)
void prep_w(const float* __restrict__ W) {
    __shared__ float tile[32][33];
    const int tx = threadIdx.x, ty = threadIdx.y;     // (32, 8)
    const int n0 = blockIdx.x * 32, k0 = blockIdx.y * 32;
#pragma unroll
    for (int i = 0; i < 32; i += 8)
        tile[ty + i][tx] = W[(size_t)(k0 + ty + i) * HDIM + n0 + tx];
    __syncthreads();
#pragma unroll
    for (int i = 0; i < 32; i += 8) {
        const int n = n0 + ty + i, k = k0 + tx;
        g_Wt[(size_t)n * HDIM + k] = __float2half_rn(tile[tx][ty + i]);
    }
}

// ===================== fused: A fp16 convert + sparse head =====================
__global__ __launch_bounds__(256)
void split_scatter(const float* __restrict__ hs, const int* __restrict__ idw,
                   const float* __restrict__ sw, const float* __restrict__ sb,
                   float* __restrict__ sp) {
    __shared__ float wsh[HDIM];
    const int t = threadIdx.x;
    ((float4*)wsh)[t] = ((const float4*)sw)[t];
    __syncthreads();

    const int lane = t & 31;
    const int wp   = t >> 5;

    // int64-vs-int32 layout detection (int64 ids < 2^31 have zero high words)
    const int odd = idw[2 * lane + 1];
    const bool is64 = __all_sync(0xFFFFFFFFu, odd == 0);

    const int tok = blockIdx.x * 8 + wp;
    const float* row = hs + (size_t)tok * HDIM;
    __half* ah = g_Ah + (size_t)tok * HDIM;

    float s = 0.f;
#pragma unroll
    for (int j = 0; j < 8; j++) {
        const int off = lane * 4 + j * 128;
        const float4 h  = *(const float4*)(row + off);
        const float4 ww = *(const float4*)(wsh + off);
        s += h.x * ww.x + h.y * ww.y + h.z * ww.z + h.w * ww.w;
        *(uint2*)(ah + off) = make_uint2(hpack(h.x, h.y), hpack(h.z, h.w));
    }
#pragma unroll
    for (int o = 16; o > 0; o >>= 1) s += __shfl_xor_sync(0xFFFFFFFFu, s, o);

    if (lane == 0) {
        const float val = s + sb[0];
        if (val > 0.f) {
            long long id = is64 ? ((const long long*)idw)[tok] : (long long)idw[tok];
            // ids 0..3 are the special tokens (cls/pad/eos/unk) -> stay zero
            if (id >= 4 && id < VOCAB) {
                const int b = tok >> 11;
                atomicMax((int*)&sp[(size_t)b * VOCAB + (int)id], __float_as_int(val));
            }
        }
    }
}

// ===================== colbert GEMM via mma.sync fp16, 64x64 warp tiles =====================
// C[m,n] = A[mrow(m),:] . W[:,n] + bias[n],  mrow(m) = m + m/2047 + 1
#define BM 128
#define BN 256
#define BKC 32                       // fp16 k per chunk
#define NC  (HDIM / BKC)             // 32 chunks
#define STAGES 4
#define ROWB 80                      // padded smem row bytes (32 f16 data + 16B pad)
#define A_PLANE (BM * ROWB)          // 10240 B
#define B_PLANE (BN * ROWB)          // 20480 B
#define STAGE (A_PLANE + B_PLANE)    // 30720 B
#define GEMM_SMEM (STAGES * STAGE)   // 122880 B

__global__ __launch_bounds__(256, 1)
void colbert_gemm_mma(const float* __restrict__ bias, __half* __restrict__ C) {
    extern __shared__ char smem[];
    const uint32_t sb = smem_u32(smem);
    const int t = threadIdx.x, lane = t & 31, wid = t >> 5;
    const int m0 = blockIdx.y * BM;
    const int n0 = blockIdx.x * BN;

    // ---- load mapping (per thread): row lr = t>>1, 32B half lh = t&1 ----
    const int lr = t >> 1, lh = t & 1;
    const int am = m0 + lr;
    const int arow = (am < MROWS) ? (am + am / SM1 + 1) : 0;
    const __half* gah  = g_Ah + (size_t)arow * HDIM + lh * 16;
    const __half* gbh  = g_Wt + (size_t)(n0 + lr) * HDIM + lh * 16;        // B rows lr
    const __half* gbh2 = g_Wt + (size_t)(n0 + lr + 128) * HDIM + lh * 16;  // B rows lr+128
    const uint32_t s_row = (uint32_t)lr * ROWB + (uint32_t)lh * 32;

    // ---- warp compute mapping: 2(m) x 4(n) warps; warp tile 64x64 ----
    const int wm = wid >> 2, wn = wid & 3;
    const uint32_t a_r  = (uint32_t)((lane & 7) + ((lane >> 3) & 1) * 8);
    const uint32_t a_kb = (uint32_t)((lane >> 4) * 16);
    const uint32_t b_r  = (uint32_t)((lane & 7) + ((lane >> 4) & 1) * 8);
    const uint32_t b_kb = (uint32_t)(((lane >> 3) & 1) * 16);

    float d[4][8][4];
#pragma unroll
    for (int i = 0; i < 4; i++)
#pragma unroll
        for (int j = 0; j < 8; j++)
#pragma unroll
            for (int q = 0; q < 4; q++) d[i][j][q] = 0.f;

    // ---- per-chunk load issue: A (2) + B (4) cp.16 per thread ----
#define ISSUE_LOADS(c) do {                                                  \
        const int _c = (c);                                                  \
        const uint32_t _sA  = sb + (uint32_t)(_c & (STAGES - 1)) * STAGE + s_row; \
        const uint32_t _sB  = _sA + A_PLANE;                                 \
        const uint32_t _sB2 = _sB + 128 * ROWB;                              \
        const __half* _ah  = gah  + _c * BKC;                                \
        const __half* _bh  = gbh  + _c * BKC;                                \
        const __half* _bh2 = gbh2 + _c * BKC;                                \
        CP_ASYNC16(_sA,       _ah);                                          \
        CP_ASYNC16(_sA + 16,  _ah + 8);                                      \
        CP_ASYNC16(_sB,       _bh);                                          \
        CP_ASYNC16(_sB + 16,  _bh + 8);                                      \
        CP_ASYNC16(_sB2,      _bh2);                                         \
        CP_ASYNC16(_sB2 + 16, _bh2 + 8);                                     \
    } while (0)

    // ---- prologue: fill STAGES-1 stages ----
#pragma unroll
    for (int c = 0; c < STAGES - 1; c++) {
        ISSUE_LOADS(c);
        CP_COMMIT();
    }

    // ---- main loop ----
    for (int c = 0; c < NC; c++) {
        CP_WAIT2();
        __syncthreads();

        if (c + STAGES - 1 < NC) ISSUE_LOADS(c + STAGES - 1);
        CP_COMMIT();

        const uint32_t st = sb + (uint32_t)(c & (STAGES - 1)) * STAGE;
        const uint32_t aA = st + (uint32_t)(wm * 64) * ROWB + a_r * ROWB + a_kb;
        const uint32_t aB = st + A_PLANE + (uint32_t)(wn * 64) * ROWB + b_r * ROWB + b_kb;
#pragma unroll
        for (int k16 = 0; k16 < 2; k16++) {
            const uint32_t ko = (uint32_t)(k16 * 32);
            unsigned ah[4][4], bh[4][4];
#pragma unroll
            for (int mt = 0; mt < 4; mt++)
                LDSM4(ah[mt], aA + (uint32_t)(mt * 16) * ROWB + ko);
#pragma unroll
            for (int p = 0; p < 4; p++)
                LDSM4(bh[p], aB + (uint32_t)(p * 16) * ROWB + ko);
#pragma unroll
            for (int mt = 0; mt < 4; mt++)
#pragma unroll
                for (int p = 0; p < 4; p++) {
                    MMA16816(d[mt][2 * p],     ah[mt], bh[p][0], bh[p][1]);
                    MMA16816(d[mt][2 * p + 1], ah[mt], bh[p][2], bh[p][3]);
                }
        }
    }
#undef ISSUE_LOADS

    // ---------------- epilogue: + bias, store fp16 raw C ----------------
    {
        const int row = lane >> 2, col2 = (lane & 3) * 2;
        const int nb = n0 + wn * 64;
#pragma unroll
        for (int nt = 0; nt < 8; nt++) {
            const int n = nb + nt * 8 + col2;
            const float b0 = __ldg(bias + n);
            const float b1 = __ldg(bias + n + 1);
#pragma unroll
            for (int mt = 0; mt < 4; mt++) {
                const int m = m0 + wm * 64 + mt * 16 + row;
                if (m < MROWS)
                    *(unsigned*)(C + (size_t)m * HDIM + n) =
                        hpack(d[mt][nt][0] + b0, d[mt][nt][1] + b1);
                if (m + 8 < MROWS)
                    *(unsigned*)(C + (size_t)(m + 8) * HDIM + n) =
                        hpack(d[mt][nt][2] + b0, d[mt][nt][3] + b1);
            }
        }
    }
}

// ===================== mask + L2 normalize colbert rows (half in, f32 out) =====================
__global__ __launch_bounds__(256)
void colbert_norm(const __half* __restrict__ Craw, const float* __restrict__ mask,
                  float* __restrict__ out) {
    const int r = blockIdx.x;
    const int b = r / SM1;
    const int s = r - b * SM1 + 1;
    const float mk = mask[b * SEQ + s];
    const int t = threadIdx.x;
    const uint2 pk = ((const uint2*)(Craw + (size_t)r * HDIM))[t];
    float2 v01 = __half22float2(*(const __half2*)&pk.x);
    float2 v23 = __half22float2(*(const __half2*)&pk.y);
    float4 v = make_float4(v01.x * mk, v01.y * mk, v23.x * mk, v23.y * mk);
    float ss = v.x * v.x + v.y * v.y + v.z * v.z + v.w * v.w;
#pragma unroll
    for (int o = 16; o > 0; o >>= 1) ss += __shfl_xor_sync(0xFFFFFFFFu, ss, o);
    __shared__ float ws[8];
    __shared__ float sscale;
    if ((t & 31) == 0) ws[t >> 5] = ss;
    __syncthreads();
    if (t == 0) {
        float tot = 0.f;
#pragma unroll
        for (int i = 0; i < 8; i++) tot += ws[i];
        sscale = 1.f / fmaxf(sqrtf(tot), EPSN);
    }
    __syncthreads();
    const float sc = sscale;
    v.x *= sc; v.y *= sc; v.z *= sc; v.w *= sc;
    ((float4*)(out + (size_t)r * HDIM))[t] = v;
}

// ===================== dense head =====================
__global__ __launch_bounds__(256)
void dense_norm(const float* __restrict__ hs, float* __restrict__ o) {
    const int b = blockIdx.x;
    const int t = threadIdx.x;
    const float4* row = (const float4*)(hs + (size_t)b * SEQ * HDIM);
    float4 v = row[t];
    float ss = v.x * v.x + v.y * v.y + v.z * v.z + v.w * v.w;
#pragma unroll
    for (int o2 = 16; o2 > 0; o2 >>= 1) ss += __shfl_xor_sync(0xFFFFFFFFu, ss, o2);
    __shared__ float ws[8];
    __shared__ float sscale;
    if ((t & 31) == 0) ws[t >> 5] = ss;
    __syncthreads();
    if (t == 0) {
        float tot = 0.f;
#pragma unroll
        for (int i = 0; i < 8; i++) tot += ws[i];
        sscale = 1.f / fmaxf(sqrtf(tot), EPSN);
    }
    __syncthreads();
    const float sc = sscale;
    v.x *= sc; v.y *= sc; v.z *= sc; v.w *= sc;
    ((float4*)(o + (size_t)b * HDIM))[t] = v;
}

// ===================== sparse zero =====================
__global__ __launch_bounds__(512)
void sparse_zero(float4* __restrict__ p) {
    const int n = (BATCH * VOCAB) / 4;  // exact
    const float4 z = make_float4(0.f, 0.f, 0.f, 0.f);
    for (int i = blockIdx.x * blockDim.x + threadIdx.x; i < n; i += gridDim.x * blockDim.x)
        p[i] = z;
}

// ===================== launch =====================
extern "C" void kernel_launch(void* const* d_in, const int* in_sizes, int n_in,
                              void* d_out, int out_size) {
    const float* hs   = (const float*)d_in[0];
    const float* mask = (const float*)d_in[1];
    const int*   ids  = (const int*)d_in[2];
    const float* sW   = (const float*)d_in[3];
    const float* sbp  = (const float*)d_in[4];
    const float* cW   = (const float*)d_in[5];
    const float* cb   = (const float*)d_in[6];

    float* out      = (float*)d_out;
    float* o_dense  = out;
    float* o_sparse = out + (size_t)BATCH * HDIM;
    float* o_col    = o_sparse + (size_t)BATCH * VOCAB;

    __half* craw = nullptr;
    cudaGetSymbolAddress((void**)&craw, g_Craw);

    cudaFuncSetAttribute(colbert_gemm_mma, cudaFuncAttributeMaxDynamicSharedMemorySize, GEMM_SMEM);

    dense_norm<<<BATCH, 256>>>(hs, o_dense);
    sparse_zero<<<2048, 512>>>((float4*)o_sparse);
    prep_w<<<dim3(32, 32), dim3(32, 8)>>>(cW);
    split_scatter<<<NTOK / 8, 256>>>(hs, ids, sW, sbp, o_sparse);

    dim3 grid(HDIM / BN, (MROWS + BM - 1) / BM);   // (4, 256)
    colbert_gemm_mma<<<grid, 256, GEMM_SMEM>>>(cb, craw);

    colbert_norm<<<MROWS, 256>>>(craw, mask, o_col);
}